// round 1
// baseline (speedup 1.0000x reference)
#include <cuda_runtime.h>
#include <math.h>

#define B_SZ 2
#define S_LEN 2048
#define NH 16
#define DH 64
#define DM 1024
#define M_ROWS (B_SZ * S_LEN)          // 4096
#define OUT_ELEMS (B_SZ * S_LEN * DM)  // 4,194,304

// Scratch (allocation-free rule: device globals)
__device__ float g_q[B_SZ * NH * S_LEN * DH];
__device__ float g_k[B_SZ * NH * S_LEN * DH];
__device__ float g_v[B_SZ * NH * S_LEN * DH];
__device__ float g_o[B_SZ * S_LEN * DM];

// ---------------------------------------------------------------------------
// Generic 64x64-tile GEMM: C = A[M,K] @ W[K,N] + bias[N]
// headsplit=1: store into [B, H, S, DH] layout (for q/k/v projections)
// headsplit=0: store row-major [M, N]
// block = 256 threads, each computes 4x4 outputs.
// ---------------------------------------------------------------------------
__global__ void gemm64(const float* __restrict__ A, const float* __restrict__ W,
                       const float* __restrict__ bias, float* __restrict__ C,
                       int M, int K, int N, int headsplit)
{
    __shared__ float As[64][17];
    __shared__ float Ws[16][65];

    const int tid = threadIdx.x;
    const int tx = tid & 15, ty = tid >> 4;
    const int bm = blockIdx.x * 64;
    const int bn = blockIdx.y * 64;

    float acc[4][4] = {};

    for (int k0 = 0; k0 < K; k0 += 16) {
        #pragma unroll
        for (int i = 0; i < 4; i++) {
            int lin = tid + i * 256;          // 0..1023
            int r = lin >> 4, c = lin & 15;   // 64 x 16
            As[r][c] = A[(size_t)(bm + r) * K + k0 + c];
        }
        #pragma unroll
        for (int i = 0; i < 4; i++) {
            int lin = tid + i * 256;
            int r = lin >> 6, c = lin & 63;   // 16 x 64
            Ws[r][c] = W[(size_t)(k0 + r) * N + bn + c];
        }
        __syncthreads();

        #pragma unroll
        for (int kk = 0; kk < 16; kk++) {
            float a[4], w[4];
            #pragma unroll
            for (int i = 0; i < 4; i++) a[i] = As[ty * 4 + i][kk];
            #pragma unroll
            for (int j = 0; j < 4; j++) w[j] = Ws[kk][tx * 4 + j];
            #pragma unroll
            for (int i = 0; i < 4; i++)
                #pragma unroll
                for (int j = 0; j < 4; j++)
                    acc[i][j] = fmaf(a[i], w[j], acc[i][j]);
        }
        __syncthreads();
    }

    #pragma unroll
    for (int i = 0; i < 4; i++) {
        int row = bm + ty * 4 + i;
        #pragma unroll
        for (int j = 0; j < 4; j++) {
            int col = bn + tx * 4 + j;
            float val = acc[i][j] + bias[col];
            if (headsplit) {
                int b = row >> 11;        // row / S_LEN
                int s = row & 2047;
                int h = col >> 6;         // col / DH
                int d = col & 63;
                g_q[0]; // no-op (keeps symbol referenced pattern trivial)
                C[(((size_t)b * NH + h) * S_LEN + s) * DH + d] = val;
            } else {
                C[(size_t)row * N + col] = val;
            }
        }
    }
}

// ---------------------------------------------------------------------------
// Batched scores: for each bh, attn[bh] = scale * q[bh] @ k[bh]^T
// q,k: [BH, S, DH]; attn: [BH, S, S]. Tile 64x64, K=64 in one shot.
// ---------------------------------------------------------------------------
__global__ void scores_kernel(const float* __restrict__ q, const float* __restrict__ k,
                              float* __restrict__ attn, float scale)
{
    const int bh = blockIdx.z;
    const float* qb = q + (size_t)bh * S_LEN * DH;
    const float* kb = k + (size_t)bh * S_LEN * DH;
    float* ab = attn + (size_t)bh * S_LEN * S_LEN;

    __shared__ float Qs[64][65];
    __shared__ float Ks[64][65];

    const int tid = threadIdx.x;
    const int bm = blockIdx.y * 64;
    const int bn = blockIdx.x * 64;

    #pragma unroll
    for (int i = 0; i < 16; i++) {
        int lin = tid + i * 256;          // 0..4095
        int r = lin >> 6, c = lin & 63;
        Qs[r][c] = qb[(size_t)(bm + r) * DH + c];
        Ks[r][c] = kb[(size_t)(bn + r) * DH + c];
    }
    __syncthreads();

    const int tx = tid & 15, ty = tid >> 4;
    float acc[4][4] = {};

    #pragma unroll 8
    for (int kk = 0; kk < 64; kk++) {
        float a[4], b[4];
        #pragma unroll
        for (int i = 0; i < 4; i++) a[i] = Qs[ty * 4 + i][kk];
        #pragma unroll
        for (int j = 0; j < 4; j++) b[j] = Ks[tx * 4 + j][kk];
        #pragma unroll
        for (int i = 0; i < 4; i++)
            #pragma unroll
            for (int j = 0; j < 4; j++)
                acc[i][j] = fmaf(a[i], b[j], acc[i][j]);
    }

    #pragma unroll
    for (int i = 0; i < 4; i++) {
        size_t rbase = (size_t)(bm + ty * 4 + i) * S_LEN + bn;
        #pragma unroll
        for (int j = 0; j < 4; j++)
            ab[rbase + tx * 4 + j] = acc[i][j] * scale;
    }
}

// ---------------------------------------------------------------------------
// Row softmax over last dim (2048). One block (256 thr) per row, float4 I/O.
// ---------------------------------------------------------------------------
__global__ void softmax2048(float* __restrict__ attn)
{
    __shared__ float red[256];
    float* p = attn + (size_t)blockIdx.x * S_LEN;
    const int tid = threadIdx.x;

    float4 x0 = ((const float4*)p)[tid];
    float4 x1 = ((const float4*)p)[tid + 256];

    float m = fmaxf(fmaxf(fmaxf(x0.x, x0.y), fmaxf(x0.z, x0.w)),
                    fmaxf(fmaxf(x1.x, x1.y), fmaxf(x1.z, x1.w)));
    red[tid] = m;
    __syncthreads();
    #pragma unroll
    for (int s = 128; s > 0; s >>= 1) {
        if (tid < s) red[tid] = fmaxf(red[tid], red[tid + s]);
        __syncthreads();
    }
    m = red[0];
    __syncthreads();

    x0.x = expf(x0.x - m); x0.y = expf(x0.y - m);
    x0.z = expf(x0.z - m); x0.w = expf(x0.w - m);
    x1.x = expf(x1.x - m); x1.y = expf(x1.y - m);
    x1.z = expf(x1.z - m); x1.w = expf(x1.w - m);

    float sum = x0.x + x0.y + x0.z + x0.w + x1.x + x1.y + x1.z + x1.w;
    red[tid] = sum;
    __syncthreads();
    #pragma unroll
    for (int s = 128; s > 0; s >>= 1) {
        if (tid < s) red[tid] += red[tid + s];
        __syncthreads();
    }
    float inv = 1.0f / red[0];

    x0.x *= inv; x0.y *= inv; x0.z *= inv; x0.w *= inv;
    x1.x *= inv; x1.y *= inv; x1.z *= inv; x1.w *= inv;

    ((float4*)p)[tid] = x0;
    ((float4*)p)[tid + 256] = x1;
}

// ---------------------------------------------------------------------------
// Batched AV: out[bh][S,DH] = attn[bh][S,S] @ v[bh][S,DH]
// Stores directly into concat-head layout g_o[(b*S+s)*DM + h*DH + d].
// ---------------------------------------------------------------------------
__global__ void av_kernel(const float* __restrict__ attn, const float* __restrict__ v,
                          float* __restrict__ o)
{
    const int bh = blockIdx.z;
    const int b = bh >> 4, h = bh & 15;
    const float* ab = attn + (size_t)bh * S_LEN * S_LEN;
    const float* vb = v + (size_t)bh * S_LEN * DH;

    __shared__ float Ps[64][65];
    __shared__ float Vs[64][65];

    const int tid = threadIdx.x;
    const int tx = tid & 15, ty = tid >> 4;
    const int bm = blockIdx.x * 64;

    float acc[4][4] = {};

    for (int k0 = 0; k0 < S_LEN; k0 += 64) {
        #pragma unroll
        for (int i = 0; i < 16; i++) {
            int lin = tid + i * 256;
            int r = lin >> 6, c = lin & 63;
            Ps[r][c] = ab[(size_t)(bm + r) * S_LEN + k0 + c];
            Vs[r][c] = vb[(size_t)(k0 + r) * DH + c];
        }
        __syncthreads();

        #pragma unroll 8
        for (int kk = 0; kk < 64; kk++) {
            float a[4], w[4];
            #pragma unroll
            for (int i = 0; i < 4; i++) a[i] = Ps[ty * 4 + i][kk];
            #pragma unroll
            for (int j = 0; j < 4; j++) w[j] = Vs[kk][tx * 4 + j];
            #pragma unroll
            for (int i = 0; i < 4; i++)
                #pragma unroll
                for (int j = 0; j < 4; j++)
                    acc[i][j] = fmaf(a[i], w[j], acc[i][j]);
        }
        __syncthreads();
    }

    #pragma unroll
    for (int i = 0; i < 4; i++) {
        int s = bm + ty * 4 + i;
        size_t rbase = ((size_t)b * S_LEN + s) * DM + h * DH;
        #pragma unroll
        for (int j = 0; j < 4; j++)
            o[rbase + tx * 4 + j] = acc[i][j];
    }
}

extern "C" void kernel_launch(void* const* d_in, const int* in_sizes, int n_in,
                              void* d_out, int out_size)
{
    const float* Q  = (const float*)d_in[0];
    const float* K  = (const float*)d_in[1];
    const float* V  = (const float*)d_in[2];
    const float* Wq = (const float*)d_in[3];
    const float* bq = (const float*)d_in[4];
    const float* Wk = (const float*)d_in[5];
    const float* bk = (const float*)d_in[6];
    const float* Wv = (const float*)d_in[7];
    const float* bv = (const float*)d_in[8];
    const float* Wo = (const float*)d_in[9];
    const float* bo = (const float*)d_in[10];

    float* out  = (float*)d_out;                 // [B, S, DM]
    float* attn = out + OUT_ELEMS;               // [B, H, S, S]

    float *gq, *gk, *gv, *go;
    cudaGetSymbolAddress((void**)&gq, g_q);
    cudaGetSymbolAddress((void**)&gk, g_k);
    cudaGetSymbolAddress((void**)&gv, g_v);
    cudaGetSymbolAddress((void**)&go, g_o);

    dim3 blk(256);
    dim3 gproj(M_ROWS / 64, DM / 64);            // (64, 16)

    // QKV projections (head-split layout)
    gemm64<<<gproj, blk>>>(Q, Wq, bq, gq, M_ROWS, DM, DM, 1);
    gemm64<<<gproj, blk>>>(K, Wk, bk, gk, M_ROWS, DM, DM, 1);
    gemm64<<<gproj, blk>>>(V, Wv, bv, gv, M_ROWS, DM, DM, 1);

    // Scores + scale
    dim3 gsc(S_LEN / 64, S_LEN / 64, B_SZ * NH); // (32, 32, 32)
    scores_kernel<<<gsc, blk>>>(gq, gk, attn, 0.125f); // 1/sqrt(64)

    // Softmax (in place on d_out's attn region)
    softmax2048<<<B_SZ * NH * S_LEN, 256>>>(attn);

    // attn @ v  ->  concat-head layout
    dim3 gav(S_LEN / 64, 1, B_SZ * NH);          // (32, 1, 32)
    av_kernel<<<gav, blk>>>(attn, gv, go);

    // Output projection
    gemm64<<<gproj, blk>>>(go, Wo, bo, out, M_ROWS, DM, DM, 0);
}

// round 2
// speedup vs baseline: 1.5291x; 1.5291x over previous
#include <cuda_runtime.h>
#include <math.h>

#define B_SZ 2
#define S_LEN 2048
#define NH 16
#define DH 64
#define DM 1024
#define M_ROWS (B_SZ * S_LEN)          // 4096
#define OUT_ELEMS (B_SZ * S_LEN * DM)  // 4,194,304

// Scratch (allocation-free rule: device globals)
__device__ float g_q[B_SZ * NH * S_LEN * DH];
__device__ float g_k[B_SZ * NH * S_LEN * DH];
__device__ float g_v[B_SZ * NH * S_LEN * DH];
__device__ float g_o[B_SZ * S_LEN * DM];

// ---------------------------------------------------------------------------
// Projection GEMM: C = A[4096,1024] @ W[1024,1024] + bias
// 128x128 tile, 256 threads, 8x8 micro-tile, k-tile 16.
// A stored transposed in smem ([k][m]) so micro-tile loads are LDS.128.
// headsplit=1 -> store to [B,H,S,DH]; else row-major [M,N].
// ---------------------------------------------------------------------------
__global__ __launch_bounds__(256, 2)
void gemm128(const float* __restrict__ A, const float* __restrict__ W,
             const float* __restrict__ bias, float* __restrict__ C,
             int headsplit)
{
    __shared__ float As[16][132];   // [k][m]
    __shared__ float Bs[16][132];   // [k][n]

    const int tid = threadIdx.x;
    const int bm = blockIdx.x * 128;
    const int bn = blockIdx.y * 128;
    const int tx = tid & 15;        // n group
    const int ty = tid >> 4;        // m group

    float acc[8][8] = {};

    for (int k0 = 0; k0 < DM; k0 += 16) {
        // A: 128 rows x 16 cols -> transposed into As[k][m]
        #pragma unroll
        for (int i = 0; i < 2; i++) {
            int lin = tid + i * 256;          // 0..511
            int r = lin >> 2;                 // 0..127
            int c4 = lin & 3;                 // 0..3
            float4 v = *(const float4*)&A[(size_t)(bm + r) * DM + k0 + c4 * 4];
            As[c4 * 4 + 0][r] = v.x;
            As[c4 * 4 + 1][r] = v.y;
            As[c4 * 4 + 2][r] = v.z;
            As[c4 * 4 + 3][r] = v.w;
        }
        // B: 16 rows x 128 cols, natural layout
        #pragma unroll
        for (int i = 0; i < 2; i++) {
            int lin = tid + i * 256;
            int r = lin >> 5;                 // 0..15
            int c4 = lin & 31;                // 0..31
            *(float4*)&Bs[r][c4 * 4] =
                *(const float4*)&W[(size_t)(k0 + r) * DM + bn + c4 * 4];
        }
        __syncthreads();

        #pragma unroll
        for (int kk = 0; kk < 16; kk++) {
            float a[8], b[8];
            *(float4*)&a[0] = *(const float4*)&As[kk][ty * 8];
            *(float4*)&a[4] = *(const float4*)&As[kk][ty * 8 + 4];
            *(float4*)&b[0] = *(const float4*)&Bs[kk][tx * 8];
            *(float4*)&b[4] = *(const float4*)&Bs[kk][tx * 8 + 4];
            #pragma unroll
            for (int i = 0; i < 8; i++)
                #pragma unroll
                for (int j = 0; j < 8; j++)
                    acc[i][j] = fmaf(a[i], b[j], acc[i][j]);
        }
        __syncthreads();
    }

    float bb[8];
    *(float4*)&bb[0] = *(const float4*)&bias[bn + tx * 8];
    *(float4*)&bb[4] = *(const float4*)&bias[bn + tx * 8 + 4];

    #pragma unroll
    for (int i = 0; i < 8; i++) {
        int row = bm + ty * 8 + i;
        int col0 = bn + tx * 8;
        float4 v0, v1;
        v0.x = acc[i][0] + bb[0]; v0.y = acc[i][1] + bb[1];
        v0.z = acc[i][2] + bb[2]; v0.w = acc[i][3] + bb[3];
        v1.x = acc[i][4] + bb[4]; v1.y = acc[i][5] + bb[5];
        v1.z = acc[i][6] + bb[6]; v1.w = acc[i][7] + bb[7];
        if (headsplit) {
            int b = row >> 11;           // / S_LEN
            int s = row & (S_LEN - 1);
            int h = col0 >> 6;           // / DH  (whole 8-span stays in one head)
            int d = col0 & 63;
            size_t base = (((size_t)b * NH + h) * S_LEN + s) * DH + d;
            *(float4*)&C[base]     = v0;
            *(float4*)&C[base + 4] = v1;
        } else {
            size_t base = (size_t)row * DM + col0;
            *(float4*)&C[base]     = v0;
            *(float4*)&C[base + 4] = v1;
        }
    }
}

// ---------------------------------------------------------------------------
// Scores: attn[bh] = scale * q[bh] @ k[bh]^T     q,k: [BH, S, DH]
// 128x128 tile, 8x8 micro, k-tile 32 (K=64 total -> 2 iters).
// Both operands transposed in smem to [k][m]/[k][n].
// ---------------------------------------------------------------------------
__global__ __launch_bounds__(256, 2)
void scores_kernel(const float* __restrict__ q, const float* __restrict__ k,
                   float* __restrict__ attn, float scale)
{
    __shared__ float Qs[32][132];   // [k][m]
    __shared__ float Ks[32][132];   // [k][n]

    const int bh = blockIdx.z;
    const float* qb = q + (size_t)bh * S_LEN * DH;
    const float* kb = k + (size_t)bh * S_LEN * DH;
    float* ab = attn + (size_t)bh * S_LEN * S_LEN;

    const int tid = threadIdx.x;
    const int bm = blockIdx.y * 128;
    const int bn = blockIdx.x * 128;
    const int tx = tid & 15;
    const int ty = tid >> 4;

    float acc[8][8] = {};

    for (int k0 = 0; k0 < DH; k0 += 32) {
        #pragma unroll
        for (int i = 0; i < 4; i++) {
            int lin = tid + i * 256;          // 0..1023
            int r = lin >> 3;                 // 0..127
            int c4 = lin & 7;                 // 0..7
            float4 vq = *(const float4*)&qb[(size_t)(bm + r) * DH + k0 + c4 * 4];
            float4 vk = *(const float4*)&kb[(size_t)(bn + r) * DH + k0 + c4 * 4];
            Qs[c4 * 4 + 0][r] = vq.x; Qs[c4 * 4 + 1][r] = vq.y;
            Qs[c4 * 4 + 2][r] = vq.z; Qs[c4 * 4 + 3][r] = vq.w;
            Ks[c4 * 4 + 0][r] = vk.x; Ks[c4 * 4 + 1][r] = vk.y;
            Ks[c4 * 4 + 2][r] = vk.z; Ks[c4 * 4 + 3][r] = vk.w;
        }
        __syncthreads();

        #pragma unroll
        for (int kk = 0; kk < 32; kk++) {
            float a[8], b[8];
            *(float4*)&a[0] = *(const float4*)&Qs[kk][ty * 8];
            *(float4*)&a[4] = *(const float4*)&Qs[kk][ty * 8 + 4];
            *(float4*)&b[0] = *(const float4*)&Ks[kk][tx * 8];
            *(float4*)&b[4] = *(const float4*)&Ks[kk][tx * 8 + 4];
            #pragma unroll
            for (int i = 0; i < 8; i++)
                #pragma unroll
                for (int j = 0; j < 8; j++)
                    acc[i][j] = fmaf(a[i], b[j], acc[i][j]);
        }
        __syncthreads();
    }

    #pragma unroll
    for (int i = 0; i < 8; i++) {
        size_t base = (size_t)(bm + ty * 8 + i) * S_LEN + bn + tx * 8;
        float4 v0, v1;
        v0.x = acc[i][0] * scale; v0.y = acc[i][1] * scale;
        v0.z = acc[i][2] * scale; v0.w = acc[i][3] * scale;
        v1.x = acc[i][4] * scale; v1.y = acc[i][5] * scale;
        v1.z = acc[i][6] * scale; v1.w = acc[i][7] * scale;
        *(float4*)&ab[base]     = v0;
        *(float4*)&ab[base + 4] = v1;
    }
}

// ---------------------------------------------------------------------------
// Row softmax over last dim (2048). One block (256 thr) per row.
// ---------------------------------------------------------------------------
__global__ __launch_bounds__(256)
void softmax2048(float* __restrict__ attn)
{
    __shared__ float red[256];
    float* p = attn + (size_t)blockIdx.x * S_LEN;
    const int tid = threadIdx.x;

    float4 x0 = ((const float4*)p)[tid];
    float4 x1 = ((const float4*)p)[tid + 256];

    float m = fmaxf(fmaxf(fmaxf(x0.x, x0.y), fmaxf(x0.z, x0.w)),
                    fmaxf(fmaxf(x1.x, x1.y), fmaxf(x1.z, x1.w)));
    red[tid] = m;
    __syncthreads();
    #pragma unroll
    for (int s = 128; s > 0; s >>= 1) {
        if (tid < s) red[tid] = fmaxf(red[tid], red[tid + s]);
        __syncthreads();
    }
    m = red[0];
    __syncthreads();

    x0.x = __expf(x0.x - m); x0.y = __expf(x0.y - m);
    x0.z = __expf(x0.z - m); x0.w = __expf(x0.w - m);
    x1.x = __expf(x1.x - m); x1.y = __expf(x1.y - m);
    x1.z = __expf(x1.z - m); x1.w = __expf(x1.w - m);

    float sum = x0.x + x0.y + x0.z + x0.w + x1.x + x1.y + x1.z + x1.w;
    red[tid] = sum;
    __syncthreads();
    #pragma unroll
    for (int s = 128; s > 0; s >>= 1) {
        if (tid < s) red[tid] += red[tid + s];
        __syncthreads();
    }
    float inv = 1.0f / red[0];

    x0.x *= inv; x0.y *= inv; x0.z *= inv; x0.w *= inv;
    x1.x *= inv; x1.y *= inv; x1.z *= inv; x1.w *= inv;

    ((float4*)p)[tid] = x0;
    ((float4*)p)[tid + 256] = x1;
}

// ---------------------------------------------------------------------------
// AV: o[bh] = attn[bh][S,S] @ v[bh][S,DH] -> concat-head layout
// Tile 256(m) x 64(n), 256 threads, 8x8 micro (tx 0..7, ty 0..31), k-tile 32.
// ---------------------------------------------------------------------------
__global__ __launch_bounds__(256, 2)
void av_kernel(const float* __restrict__ attn, const float* __restrict__ v,
               float* __restrict__ o)
{
    __shared__ float Ps[32][260];   // [k][m]
    __shared__ float Vs[32][68];    // [k][n]

    const int bh = blockIdx.z;
    const int b = bh >> 4, h = bh & 15;
    const float* ab = attn + (size_t)bh * S_LEN * S_LEN;
    const float* vb = v + (size_t)bh * S_LEN * DH;

    const int tid = threadIdx.x;
    const int bm = blockIdx.x * 256;
    const int tx = tid & 7;         // n group (0..7)
    const int ty = tid >> 3;        // m group (0..31)

    float acc[8][8] = {};

    for (int k0 = 0; k0 < S_LEN; k0 += 32) {
        // attn tile: 256 rows x 32 cols, transposed into Ps[k][m]
        #pragma unroll
        for (int i = 0; i < 8; i++) {
            int lin = tid + i * 256;          // 0..2047
            int r = lin >> 3;                 // 0..255
            int c4 = lin & 7;                 // 0..7
            float4 vp = *(const float4*)&ab[(size_t)(bm + r) * S_LEN + k0 + c4 * 4];
            Ps[c4 * 4 + 0][r] = vp.x; Ps[c4 * 4 + 1][r] = vp.y;
            Ps[c4 * 4 + 2][r] = vp.z; Ps[c4 * 4 + 3][r] = vp.w;
        }
        // v tile: 32 rows x 64 cols, natural layout
        #pragma unroll
        for (int i = 0; i < 2; i++) {
            int lin = tid + i * 256;          // 0..511
            int r = lin >> 4;                 // 0..31
            int c4 = lin & 15;                // 0..15
            *(float4*)&Vs[r][c4 * 4] =
                *(const float4*)&vb[(size_t)(k0 + r) * DH + c4 * 4];
        }
        __syncthreads();

        #pragma unroll
        for (int kk = 0; kk < 32; kk++) {
            float a[8], bb[8];
            *(float4*)&a[0] = *(const float4*)&Ps[kk][ty * 8];
            *(float4*)&a[4] = *(const float4*)&Ps[kk][ty * 8 + 4];
            *(float4*)&bb[0] = *(const float4*)&Vs[kk][tx * 8];
            *(float4*)&bb[4] = *(const float4*)&Vs[kk][tx * 8 + 4];
            #pragma unroll
            for (int i = 0; i < 8; i++)
                #pragma unroll
                for (int j = 0; j < 8; j++)
                    acc[i][j] = fmaf(a[i], bb[j], acc[i][j]);
        }
        __syncthreads();
    }

    #pragma unroll
    for (int i = 0; i < 8; i++) {
        int s = bm + ty * 8 + i;
        size_t base = ((size_t)b * S_LEN + s) * DM + h * DH + tx * 8;
        float4 v0, v1;
        v0.x = acc[i][0]; v0.y = acc[i][1]; v0.z = acc[i][2]; v0.w = acc[i][3];
        v1.x = acc[i][4]; v1.y = acc[i][5]; v1.z = acc[i][6]; v1.w = acc[i][7];
        *(float4*)&o[base]     = v0;
        *(float4*)&o[base + 4] = v1;
    }
}

extern "C" void kernel_launch(void* const* d_in, const int* in_sizes, int n_in,
                              void* d_out, int out_size)
{
    const float* Q  = (const float*)d_in[0];
    const float* K  = (const float*)d_in[1];
    const float* V  = (const float*)d_in[2];
    const float* Wq = (const float*)d_in[3];
    const float* bq = (const float*)d_in[4];
    const float* Wk = (const float*)d_in[5];
    const float* bk = (const float*)d_in[6];
    const float* Wv = (const float*)d_in[7];
    const float* bv = (const float*)d_in[8];
    const float* Wo = (const float*)d_in[9];
    const float* bo = (const float*)d_in[10];

    float* out  = (float*)d_out;                 // [B, S, DM]
    float* attn = out + OUT_ELEMS;               // [B, H, S, S]

    float *gq, *gk, *gv, *go;
    cudaGetSymbolAddress((void**)&gq, g_q);
    cudaGetSymbolAddress((void**)&gk, g_k);
    cudaGetSymbolAddress((void**)&gv, g_v);
    cudaGetSymbolAddress((void**)&go, g_o);

    dim3 blk(256);
    dim3 gproj(M_ROWS / 128, DM / 128);          // (32, 8)

    gemm128<<<gproj, blk>>>(Q, Wq, bq, gq, 1);
    gemm128<<<gproj, blk>>>(K, Wk, bk, gk, 1);
    gemm128<<<gproj, blk>>>(V, Wv, bv, gv, 1);

    dim3 gsc(S_LEN / 128, S_LEN / 128, B_SZ * NH);   // (16, 16, 32)
    scores_kernel<<<gsc, blk>>>(gq, gk, attn, 0.125f);

    softmax2048<<<B_SZ * NH * S_LEN, 256>>>(attn);

    dim3 gav(S_LEN / 256, 1, B_SZ * NH);             // (8, 1, 32)
    av_kernel<<<gav, blk>>>(attn, gv, go);

    gemm128<<<gproj, blk>>>(go, Wo, bo, out, 0);
}